// round 12
// baseline (speedup 1.0000x reference)
#include <cuda_runtime.h>
#include <cuda_bf16.h>
#include <cstdint>

// ============================================================================
// Problem: B=256, P=196, ENC=2048, WORD=512, ATT=512
//   att_enc = enc @ W_enc + b_enc              [B,P,512]  (105 GFLOP, dominant)
//   att_dec = dec @ W_dec + b_dec              [B,512]
//   att     = relu(att_enc + att_dec) . W_fin  -> [B,P]   (b_fin dropped: softmax-invariant)
//   w       = softmax_P(att)
//   out     = sum_p enc[b,p,:] * w[b,p]        [B,2048]
//
// tcgen05 is NOT available (harness ptxas targets plain sm_103, no 'a' features).
// GEMM uses mma.sync.m16n8k8 tf32 (sm_80+ feature, accepted by sm_103).
// ============================================================================

#define B_SZ   256
#define P_SZ   196
#define ENC_D  2048
#define WORD_D 512
#define ATT_D  512
#define ROWS_TOTAL (B_SZ * P_SZ)        // 50176
#define M_TILE 128
#define N_TILE 128
#define K_TILE 32
#define N_KT   (ENC_D / K_TILE)         // 64
#define M_CTAS (ROWS_TOTAL / M_TILE)    // 392
#define N_CTAS (ATT_D / N_TILE)         // 4

// ---- device scratch (no runtime allocation allowed) ----
__device__ __align__(16) float g_attdec[B_SZ * ATT_D];        // [256,512]
__device__ __align__(16) float g_attP[N_CTAS * ROWS_TOTAL];   // per-N-slice logit partials

// ============================================================================
// PTX helpers
// ============================================================================
__device__ __forceinline__ uint32_t smem_u32(const void* p) {
    uint32_t a;
    asm("{ .reg .u64 t; cvta.to.shared.u64 t, %1; cvt.u32.u64 %0, t; }" : "=r"(a) : "l"(p));
    return a;
}
#define CP_ASYNC16(dst_u32, src_ptr) \
    asm volatile("cp.async.cg.shared.global [%0], [%1], 16;" :: "r"(dst_u32), "l"(src_ptr) : "memory")
#define CP_ASYNC_COMMIT()   asm volatile("cp.async.commit_group;" ::: "memory")
#define CP_ASYNC_WAIT_ALL() asm volatile("cp.async.wait_group 0;" ::: "memory")

__device__ __forceinline__ uint32_t f2tf32(float x) {
    uint32_t y;
    asm("cvt.rna.tf32.f32 %0, %1;" : "=r"(y) : "f"(x));
    return y;
}
__device__ __forceinline__ void mma_tf32(float* d, const uint32_t* a, const uint32_t* b) {
    asm volatile(
        "mma.sync.aligned.m16n8k8.row.col.f32.tf32.tf32.f32 "
        "{%0,%1,%2,%3}, {%4,%5,%6,%7}, {%8,%9}, {%0,%1,%2,%3};"
        : "+f"(d[0]), "+f"(d[1]), "+f"(d[2]), "+f"(d[3])
        : "r"(a[0]), "r"(a[1]), "r"(a[2]), "r"(a[3]), "r"(b[0]), "r"(b[1]));
}

// ============================================================================
// SMEM layout (dynamic, bytes). Padded strides for conflict-free frag loads.
//   A tile: 128 rows x 32 k, stride 36 floats (144 B)
//   B tile:  32 k   x 128 n, stride 136 floats (544 B)
// ============================================================================
#define A_STRIDE_F 36
#define B_STRIDE_F 136
#define A_TILE_B   (M_TILE * A_STRIDE_F * 4)   // 18432
#define B_TILE_B   (K_TILE * B_STRIDE_F * 4)   // 17408
#define OFF_A(s)   ((s) * A_TILE_B)
#define OFF_B(s)   (2 * A_TILE_B + (s) * B_TILE_B)
#define OFF_ADEC0  (2 * A_TILE_B + 2 * B_TILE_B)        // 71680
#define OFF_ADEC1  (OFF_ADEC0 + 512)
#define OFF_WFIN   (OFF_ADEC0 + 1024)
#define OFF_PART   (OFF_ADEC0 + 1536)                   // 4 x 128 floats
#define SMEM_TOTAL (OFF_PART + 2048)                    // 75264

// ============================================================================
// Kernel 1: att_dec = decoder_out @ W_dec + b_dec   (4 batches / block)
// ============================================================================
__global__ void __launch_bounds__(512) decproj_kernel(
    const float* __restrict__ dec, const float* __restrict__ Wd, const float* __restrict__ bd) {
    __shared__ float sdec[4][WORD_D];
    int tid = threadIdx.x;
    int b0 = blockIdx.x * 4;
#pragma unroll
    for (int i = 0; i < 4; i++)
        sdec[i][tid] = dec[(size_t)(b0 + i) * WORD_D + tid];
    __syncthreads();
    float a0 = 0.f, a1 = 0.f, a2 = 0.f, a3 = 0.f;
#pragma unroll 4
    for (int k = 0; k < WORD_D; k++) {
        float w = Wd[(size_t)k * ATT_D + tid];
        a0 = fmaf(sdec[0][k], w, a0);
        a1 = fmaf(sdec[1][k], w, a1);
        a2 = fmaf(sdec[2][k], w, a2);
        a3 = fmaf(sdec[3][k], w, a3);
    }
    float bb = bd[tid];
    g_attdec[(size_t)(b0 + 0) * ATT_D + tid] = a0 + bb;
    g_attdec[(size_t)(b0 + 1) * ATT_D + tid] = a1 + bb;
    g_attdec[(size_t)(b0 + 2) * ATT_D + tid] = a2 + bb;
    g_attdec[(size_t)(b0 + 3) * ATT_D + tid] = a3 + bb;
}

// ============================================================================
// Kernel 2: tf32 mma.sync GEMM + fused relu/dot epilogue -> g_attP partials
//   grid (392, 4): CTA tile M=128 x N=128, K=2048 (64 stages of 32)
//   8 warps: warp_m = wid>>2 (2), warp_n = wid&3 (4); warp tile 64 x 32
// ============================================================================
__global__ void __launch_bounds__(256, 1) gemm_att_kernel(
    const float* __restrict__ enc,
    const float* __restrict__ W_enc,
    const float* __restrict__ b_enc,
    const float* __restrict__ W_fin) {
    extern __shared__ char smem[];
    const uint32_t sb = smem_u32(smem);
    const int tid = threadIdx.x;
    const int wid = tid >> 5, lane = tid & 31;
    const int warp_m = wid >> 2, warp_n = wid & 3;
    const int g = lane >> 2, tg = lane & 3;

    const int row0 = blockIdx.x * M_TILE;
    const int n0   = blockIdx.y * N_TILE;
    const int b0   = row0 / P_SZ;
    const int b1   = (row0 + M_TILE - 1) / P_SZ;

    // bias slices: sAdec = b_enc + att_dec (per batch), sWfin
    float* sAdec0 = (float*)(smem + OFF_ADEC0);
    float* sAdec1 = (float*)(smem + OFF_ADEC1);
    float* sWfin  = (float*)(smem + OFF_WFIN);
    if (tid < 128) {
        float be = b_enc[n0 + tid];
        sAdec0[tid] = be + g_attdec[(size_t)b0 * ATT_D + n0 + tid];
        sAdec1[tid] = be + g_attdec[(size_t)b1 * ATT_D + n0 + tid];
        sWfin[tid]  = W_fin[n0 + tid];
    }

    // ---- cp.async staging addresses ----
    // A: thread covers 4 float4: row = i*32 + tid/8, c4 = tid%8
    const int a_r = tid >> 3, a_c = tid & 7;
    const float* a_src = enc + (size_t)(row0 + a_r) * ENC_D + a_c * 4;
    const uint32_t a_dst = a_r * (A_STRIDE_F * 4) + a_c * 16;
    // B: thread covers 4 float4: k = i*8 + tid/32, c4 = tid%32
    const int b_k = tid >> 5, b_c = tid & 31;
    const float* b_src = W_enc + (size_t)b_k * ATT_D + n0 + b_c * 4;
    const uint32_t b_dst = b_k * (B_STRIDE_F * 4) + b_c * 16;

    // prologue: stage 0 <- tile 0
    {
        uint32_t ab = sb + OFF_A(0), bb = sb + OFF_B(0);
#pragma unroll
        for (int i = 0; i < 4; i++)
            CP_ASYNC16(ab + a_dst + i * 32 * (A_STRIDE_F * 4), a_src + (size_t)i * 32 * ENC_D);
#pragma unroll
        for (int i = 0; i < 4; i++)
            CP_ASYNC16(bb + b_dst + i * 8 * (B_STRIDE_F * 4), b_src + (size_t)i * 8 * ATT_D);
        CP_ASYNC_COMMIT();
        CP_ASYNC_WAIT_ALL();
    }
    __syncthreads();

    float acc[4][4][4];
#pragma unroll
    for (int mi = 0; mi < 4; mi++)
#pragma unroll
        for (int ni = 0; ni < 4; ni++)
#pragma unroll
            for (int r = 0; r < 4; r++) acc[mi][ni][r] = 0.f;

    // fragment smem offsets (floats)
    const int a_frag_base = (warp_m * 64 + g) * A_STRIDE_F + tg;   // + mi*16*36, + k8*8
    const int b_frag_base = tg * B_STRIDE_F + warp_n * 32 + g;     // + k8*8*136, + ni*8

    for (int c = 0; c < N_KT; ++c) {
        const int s = c & 1;
        // prefetch next tile into the other stage
        if (c + 1 < N_KT) {
            const size_t k_off = (size_t)(c + 1) * K_TILE;
            uint32_t ab = sb + OFF_A(s ^ 1), bbs = sb + OFF_B(s ^ 1);
#pragma unroll
            for (int i = 0; i < 4; i++)
                CP_ASYNC16(ab + a_dst + i * 32 * (A_STRIDE_F * 4),
                           a_src + (size_t)i * 32 * ENC_D + k_off);
#pragma unroll
            for (int i = 0; i < 4; i++)
                CP_ASYNC16(bbs + b_dst + i * 8 * (B_STRIDE_F * 4),
                           b_src + (size_t)(i * 8 + k_off) * ATT_D);
            CP_ASYNC_COMMIT();
        }

        const float* As = (const float*)(smem + OFF_A(s));
        const float* Bs = (const float*)(smem + OFF_B(s));
#pragma unroll
        for (int k8 = 0; k8 < 4; k8++) {
            uint32_t af[4][4], bf[4][2];
#pragma unroll
            for (int mi = 0; mi < 4; mi++) {
                const float* p = As + a_frag_base + mi * 16 * A_STRIDE_F + k8 * 8;
                af[mi][0] = f2tf32(p[0]);
                af[mi][1] = f2tf32(p[8 * A_STRIDE_F]);
                af[mi][2] = f2tf32(p[4]);
                af[mi][3] = f2tf32(p[8 * A_STRIDE_F + 4]);
            }
#pragma unroll
            for (int ni = 0; ni < 4; ni++) {
                const float* p = Bs + b_frag_base + k8 * 8 * B_STRIDE_F + ni * 8;
                bf[ni][0] = f2tf32(p[0]);
                bf[ni][1] = f2tf32(p[4 * B_STRIDE_F]);
            }
#pragma unroll
            for (int mi = 0; mi < 4; mi++)
#pragma unroll
                for (int ni = 0; ni < 4; ni++)
                    mma_tf32(acc[mi][ni], af[mi], bf[ni]);
        }

        if (c + 1 < N_KT) CP_ASYNC_WAIT_ALL();
        __syncthreads();
    }

    // ---- fused epilogue: relu(acc + bias + att_dec) . W_fin over this 128-n slice
    float* sPart = (float*)(smem + OFF_PART);   // [4][128]
#pragma unroll
    for (int mi = 0; mi < 4; mi++) {
        const int rl_lo = warp_m * 64 + mi * 16 + g;
        const int rl_hi = rl_lo + 8;
        const float* ad_lo = ((row0 + rl_lo) / P_SZ == b0) ? sAdec0 : sAdec1;
        const float* ad_hi = ((row0 + rl_hi) / P_SZ == b0) ? sAdec0 : sAdec1;
        float p_lo = 0.f, p_hi = 0.f;
#pragma unroll
        for (int ni = 0; ni < 4; ni++) {
            const int n = warp_n * 32 + ni * 8 + 2 * tg;
            float x;
            x = acc[mi][ni][0] + ad_lo[n];     p_lo = fmaf(fmaxf(x, 0.f), sWfin[n],     p_lo);
            x = acc[mi][ni][1] + ad_lo[n + 1]; p_lo = fmaf(fmaxf(x, 0.f), sWfin[n + 1], p_lo);
            x = acc[mi][ni][2] + ad_hi[n];     p_hi = fmaf(fmaxf(x, 0.f), sWfin[n],     p_hi);
            x = acc[mi][ni][3] + ad_hi[n + 1]; p_hi = fmaf(fmaxf(x, 0.f), sWfin[n + 1], p_hi);
        }
        // reduce over the 4 lanes of the quad
        p_lo += __shfl_xor_sync(0xffffffffu, p_lo, 1);
        p_lo += __shfl_xor_sync(0xffffffffu, p_lo, 2);
        p_hi += __shfl_xor_sync(0xffffffffu, p_hi, 1);
        p_hi += __shfl_xor_sync(0xffffffffu, p_hi, 2);
        if (tg == 0) {
            sPart[warp_n * 128 + rl_lo] = p_lo;
            sPart[warp_n * 128 + rl_hi] = p_hi;
        }
    }
    __syncthreads();
    if (tid < 128) {
        float v = sPart[tid] + sPart[128 + tid] + sPart[256 + tid] + sPart[384 + tid];
        g_attP[(size_t)blockIdx.y * ROWS_TOTAL + row0 + tid] = v;
    }
}

// ============================================================================
// Kernel 3: softmax over P + weighted sum of encoder features
//   grid (B, 2): each block does 1024 of 2048 enc dims, 256 threads x float4
// ============================================================================
__global__ void __launch_bounds__(256) softmax_wsum_kernel(
    const float* __restrict__ enc, float* __restrict__ out) {
    int b = blockIdx.x;
    int half = blockIdx.y;
    int tid = threadIdx.x;
    __shared__ float red[256];
    __shared__ float w[256];

    float v = -1e30f;
    if (tid < P_SZ) {
        size_t idx = (size_t)b * P_SZ + tid;
        v = g_attP[idx] + g_attP[ROWS_TOTAL + idx] +
            g_attP[2 * ROWS_TOTAL + idx] + g_attP[3 * ROWS_TOTAL + idx];
    }
    red[tid] = v;
    __syncthreads();
    for (int s = 128; s > 0; s >>= 1) {
        if (tid < s) red[tid] = fmaxf(red[tid], red[tid + s]);
        __syncthreads();
    }
    float m = red[0];
    __syncthreads();
    float e = (tid < P_SZ) ? expf(v - m) : 0.f;
    red[tid] = e;
    __syncthreads();
    for (int s = 128; s > 0; s >>= 1) {
        if (tid < s) red[tid] += red[tid + s];
        __syncthreads();
    }
    float inv = 1.f / red[0];
    w[tid] = e * inv;
    __syncthreads();

    const float* base = enc + (size_t)b * P_SZ * ENC_D + half * 1024 + tid * 4;
    float4 acc = make_float4(0.f, 0.f, 0.f, 0.f);
#pragma unroll 4
    for (int p = 0; p < P_SZ; p++) {
        float4 x = *(const float4*)(base + (size_t)p * ENC_D);
        float wp = w[p];
        acc.x = fmaf(x.x, wp, acc.x);
        acc.y = fmaf(x.y, wp, acc.y);
        acc.z = fmaf(x.z, wp, acc.z);
        acc.w = fmaf(x.w, wp, acc.w);
    }
    *(float4*)(out + (size_t)b * ENC_D + half * 1024 + tid * 4) = acc;
}

// ============================================================================
// Launch
// ============================================================================
extern "C" void kernel_launch(void* const* d_in, const int* in_sizes, int n_in,
                              void* d_out, int out_size) {
    const float* encoder_out = (const float*)d_in[0];
    const float* decoder_out = (const float*)d_in[1];
    const float* W_enc       = (const float*)d_in[2];
    const float* b_enc       = (const float*)d_in[3];
    const float* W_dec       = (const float*)d_in[4];
    const float* b_dec       = (const float*)d_in[5];
    const float* W_fin       = (const float*)d_in[6];
    // d_in[7] = b_fin : dropped (softmax shift-invariant)
    float* out = (float*)d_out;

    decproj_kernel<<<B_SZ / 4, 512>>>(decoder_out, W_dec, b_dec);

    static int smem_set = 0;
    if (!smem_set) {
        cudaFuncSetAttribute(gemm_att_kernel, cudaFuncAttributeMaxDynamicSharedMemorySize, SMEM_TOTAL);
        smem_set = 1;
    }
    gemm_att_kernel<<<dim3(M_CTAS, N_CTAS), 256, SMEM_TOTAL>>>(encoder_out, W_enc, b_enc, W_fin);

    softmax_wsum_kernel<<<dim3(B_SZ, 2), 256>>>(encoder_out, out);
}

// round 13
// speedup vs baseline: 1.0007x; 1.0007x over previous
#include <cuda_runtime.h>
#include <cuda_bf16.h>
#include <cstdint>

// ============================================================================
// Problem: B=256, P=196, ENC=2048, WORD=512, ATT=512
//   att_enc = enc @ W_enc + b_enc              [B,P,512]  (105 GFLOP, dominant)
//   att_dec = dec @ W_dec + b_dec              [B,512]
//   att     = relu(att_enc + att_dec) . W_fin  -> [B,P]   (b_fin dropped: softmax-invariant)
//   w       = softmax_P(att)
//   out     = sum_p enc[b,p,:] * w[b,p]        [B,2048]
//
// tcgen05 is NOT available (harness ptxas targets plain sm_103, no 'a' features).
// GEMM uses mma.sync.m16n8k8 tf32 (sm_80+ feature, accepted by sm_103).
// ============================================================================

#define B_SZ   256
#define P_SZ   196
#define ENC_D  2048
#define WORD_D 512
#define ATT_D  512
#define ROWS_TOTAL (B_SZ * P_SZ)        // 50176
#define M_TILE 128
#define N_TILE 128
#define K_TILE 32
#define N_KT   (ENC_D / K_TILE)         // 64
#define M_CTAS (ROWS_TOTAL / M_TILE)    // 392
#define N_CTAS (ATT_D / N_TILE)         // 4

// ---- device scratch (no runtime allocation allowed) ----
__device__ __align__(16) float g_attdec[B_SZ * ATT_D];        // [256,512]
__device__ __align__(16) float g_attP[N_CTAS * ROWS_TOTAL];   // per-N-slice logit partials

// ============================================================================
// PTX helpers
// ============================================================================
__device__ __forceinline__ uint32_t smem_u32(const void* p) {
    uint32_t a;
    asm("{ .reg .u64 t; cvta.to.shared.u64 t, %1; cvt.u32.u64 %0, t; }" : "=r"(a) : "l"(p));
    return a;
}
#define CP_ASYNC16(dst_u32, src_ptr) \
    asm volatile("cp.async.cg.shared.global [%0], [%1], 16;" :: "r"(dst_u32), "l"(src_ptr) : "memory")
#define CP_ASYNC_COMMIT()   asm volatile("cp.async.commit_group;" ::: "memory")
#define CP_ASYNC_WAIT_ALL() asm volatile("cp.async.wait_group 0;" ::: "memory")

__device__ __forceinline__ uint32_t f2tf32(float x) {
    uint32_t y;
    asm("cvt.rna.tf32.f32 %0, %1;" : "=r"(y) : "f"(x));
    return y;
}
__device__ __forceinline__ void mma_tf32(float* d, const uint32_t* a, const uint32_t* b) {
    asm volatile(
        "mma.sync.aligned.m16n8k8.row.col.f32.tf32.tf32.f32 "
        "{%0,%1,%2,%3}, {%4,%5,%6,%7}, {%8,%9}, {%0,%1,%2,%3};"
        : "+f"(d[0]), "+f"(d[1]), "+f"(d[2]), "+f"(d[3])
        : "r"(a[0]), "r"(a[1]), "r"(a[2]), "r"(a[3]), "r"(b[0]), "r"(b[1]));
}

// ============================================================================
// SMEM layout (dynamic, bytes). Padded strides for conflict-free frag loads.
//   A tile: 128 rows x 32 k, stride 36 floats (144 B)
//   B tile:  32 k   x 128 n, stride 136 floats (544 B)
// ============================================================================
#define A_STRIDE_F 36
#define B_STRIDE_F 136
#define A_TILE_B   (M_TILE * A_STRIDE_F * 4)   // 18432
#define B_TILE_B   (K_TILE * B_STRIDE_F * 4)   // 17408
#define OFF_A(s)   ((s) * A_TILE_B)
#define OFF_B(s)   (2 * A_TILE_B + (s) * B_TILE_B)
#define OFF_ADEC0  (2 * A_TILE_B + 2 * B_TILE_B)        // 71680
#define OFF_ADEC1  (OFF_ADEC0 + 512)
#define OFF_WFIN   (OFF_ADEC0 + 1024)
#define OFF_PART   (OFF_ADEC0 + 1536)                   // 4 x 128 floats
#define SMEM_TOTAL (OFF_PART + 2048)                    // 75264

// ============================================================================
// Kernel 1: att_dec = decoder_out @ W_dec + b_dec   (4 batches / block)
// ============================================================================
__global__ void __launch_bounds__(512) decproj_kernel(
    const float* __restrict__ dec, const float* __restrict__ Wd, const float* __restrict__ bd) {
    __shared__ float sdec[4][WORD_D];
    int tid = threadIdx.x;
    int b0 = blockIdx.x * 4;
#pragma unroll
    for (int i = 0; i < 4; i++)
        sdec[i][tid] = dec[(size_t)(b0 + i) * WORD_D + tid];
    __syncthreads();
    float a0 = 0.f, a1 = 0.f, a2 = 0.f, a3 = 0.f;
#pragma unroll 4
    for (int k = 0; k < WORD_D; k++) {
        float w = Wd[(size_t)k * ATT_D + tid];
        a0 = fmaf(sdec[0][k], w, a0);
        a1 = fmaf(sdec[1][k], w, a1);
        a2 = fmaf(sdec[2][k], w, a2);
        a3 = fmaf(sdec[3][k], w, a3);
    }
    float bb = bd[tid];
    g_attdec[(size_t)(b0 + 0) * ATT_D + tid] = a0 + bb;
    g_attdec[(size_t)(b0 + 1) * ATT_D + tid] = a1 + bb;
    g_attdec[(size_t)(b0 + 2) * ATT_D + tid] = a2 + bb;
    g_attdec[(size_t)(b0 + 3) * ATT_D + tid] = a3 + bb;
}

// ============================================================================
// Kernel 2: tf32 mma.sync GEMM + fused relu/dot epilogue -> g_attP partials
//   grid (392, 4): CTA tile M=128 x N=128, K=2048 (64 stages of 32)
//   8 warps: warp_m = wid>>2 (2), warp_n = wid&3 (4); warp tile 64 x 32
// ============================================================================
__global__ void __launch_bounds__(256, 1) gemm_att_kernel(
    const float* __restrict__ enc,
    const float* __restrict__ W_enc,
    const float* __restrict__ b_enc,
    const float* __restrict__ W_fin) {
    extern __shared__ char smem[];
    const uint32_t sb = smem_u32(smem);
    const int tid = threadIdx.x;
    const int wid = tid >> 5, lane = tid & 31;
    const int warp_m = wid >> 2, warp_n = wid & 3;
    const int g = lane >> 2, tg = lane & 3;

    const int row0 = blockIdx.x * M_TILE;
    const int n0   = blockIdx.y * N_TILE;
    const int b0   = row0 / P_SZ;
    const int b1   = (row0 + M_TILE - 1) / P_SZ;

    // bias slices: sAdec = b_enc + att_dec (per batch), sWfin
    float* sAdec0 = (float*)(smem + OFF_ADEC0);
    float* sAdec1 = (float*)(smem + OFF_ADEC1);
    float* sWfin  = (float*)(smem + OFF_WFIN);
    if (tid < 128) {
        float be = b_enc[n0 + tid];
        sAdec0[tid] = be + g_attdec[(size_t)b0 * ATT_D + n0 + tid];
        sAdec1[tid] = be + g_attdec[(size_t)b1 * ATT_D + n0 + tid];
        sWfin[tid]  = W_fin[n0 + tid];
    }

    // ---- cp.async staging addresses ----
    // A: thread covers 4 float4: row = i*32 + tid/8, c4 = tid%8
    const int a_r = tid >> 3, a_c = tid & 7;
    const float* a_src = enc + (size_t)(row0 + a_r) * ENC_D + a_c * 4;
    const uint32_t a_dst = a_r * (A_STRIDE_F * 4) + a_c * 16;
    // B: thread covers 4 float4: k = i*8 + tid/32, c4 = tid%32
    const int b_k = tid >> 5, b_c = tid & 31;
    const float* b_src = W_enc + (size_t)b_k * ATT_D + n0 + b_c * 4;
    const uint32_t b_dst = b_k * (B_STRIDE_F * 4) + b_c * 16;

    // prologue: stage 0 <- tile 0
    {
        uint32_t ab = sb + OFF_A(0), bb = sb + OFF_B(0);
#pragma unroll
        for (int i = 0; i < 4; i++)
            CP_ASYNC16(ab + a_dst + i * 32 * (A_STRIDE_F * 4), a_src + (size_t)i * 32 * ENC_D);
#pragma unroll
        for (int i = 0; i < 4; i++)
            CP_ASYNC16(bb + b_dst + i * 8 * (B_STRIDE_F * 4), b_src + (size_t)i * 8 * ATT_D);
        CP_ASYNC_COMMIT();
        CP_ASYNC_WAIT_ALL();
    }
    __syncthreads();

    float acc[4][4][4];
#pragma unroll
    for (int mi = 0; mi < 4; mi++)
#pragma unroll
        for (int ni = 0; ni < 4; ni++)
#pragma unroll
            for (int r = 0; r < 4; r++) acc[mi][ni][r] = 0.f;

    // fragment smem offsets (floats)
    const int a_frag_base = (warp_m * 64 + g) * A_STRIDE_F + tg;   // + mi*16*36, + k8*8
    const int b_frag_base = tg * B_STRIDE_F + warp_n * 32 + g;     // + k8*8*136, + ni*8

    for (int c = 0; c < N_KT; ++c) {
        const int s = c & 1;
        // prefetch next tile into the other stage
        if (c + 1 < N_KT) {
            const size_t k_off = (size_t)(c + 1) * K_TILE;
            uint32_t ab = sb + OFF_A(s ^ 1), bbs = sb + OFF_B(s ^ 1);
#pragma unroll
            for (int i = 0; i < 4; i++)
                CP_ASYNC16(ab + a_dst + i * 32 * (A_STRIDE_F * 4),
                           a_src + (size_t)i * 32 * ENC_D + k_off);
#pragma unroll
            for (int i = 0; i < 4; i++)
                CP_ASYNC16(bbs + b_dst + i * 8 * (B_STRIDE_F * 4),
                           b_src + (size_t)(i * 8 + k_off) * ATT_D);
            CP_ASYNC_COMMIT();
        }

        const float* As = (const float*)(smem + OFF_A(s));
        const float* Bs = (const float*)(smem + OFF_B(s));
#pragma unroll
        for (int k8 = 0; k8 < 4; k8++) {
            uint32_t af[4][4], bf[4][2];
#pragma unroll
            for (int mi = 0; mi < 4; mi++) {
                const float* p = As + a_frag_base + mi * 16 * A_STRIDE_F + k8 * 8;
                af[mi][0] = f2tf32(p[0]);
                af[mi][1] = f2tf32(p[8 * A_STRIDE_F]);
                af[mi][2] = f2tf32(p[4]);
                af[mi][3] = f2tf32(p[8 * A_STRIDE_F + 4]);
            }
#pragma unroll
            for (int ni = 0; ni < 4; ni++) {
                const float* p = Bs + b_frag_base + k8 * 8 * B_STRIDE_F + ni * 8;
                bf[ni][0] = f2tf32(p[0]);
                bf[ni][1] = f2tf32(p[4 * B_STRIDE_F]);
            }
#pragma unroll
            for (int mi = 0; mi < 4; mi++)
#pragma unroll
                for (int ni = 0; ni < 4; ni++)
                    mma_tf32(acc[mi][ni], af[mi], bf[ni]);
        }

        if (c + 1 < N_KT) CP_ASYNC_WAIT_ALL();
        __syncthreads();
    }

    // ---- fused epilogue: relu(acc + bias + att_dec) . W_fin over this 128-n slice
    float* sPart = (float*)(smem + OFF_PART);   // [4][128]
#pragma unroll
    for (int mi = 0; mi < 4; mi++) {
        const int rl_lo = warp_m * 64 + mi * 16 + g;
        const int rl_hi = rl_lo + 8;
        const float* ad_lo = ((row0 + rl_lo) / P_SZ == b0) ? sAdec0 : sAdec1;
        const float* ad_hi = ((row0 + rl_hi) / P_SZ == b0) ? sAdec0 : sAdec1;
        float p_lo = 0.f, p_hi = 0.f;
#pragma unroll
        for (int ni = 0; ni < 4; ni++) {
            const int n = warp_n * 32 + ni * 8 + 2 * tg;
            float x;
            x = acc[mi][ni][0] + ad_lo[n];     p_lo = fmaf(fmaxf(x, 0.f), sWfin[n],     p_lo);
            x = acc[mi][ni][1] + ad_lo[n + 1]; p_lo = fmaf(fmaxf(x, 0.f), sWfin[n + 1], p_lo);
            x = acc[mi][ni][2] + ad_hi[n];     p_hi = fmaf(fmaxf(x, 0.f), sWfin[n],     p_hi);
            x = acc[mi][ni][3] + ad_hi[n + 1]; p_hi = fmaf(fmaxf(x, 0.f), sWfin[n + 1], p_hi);
        }
        // reduce over the 4 lanes of the quad
        p_lo += __shfl_xor_sync(0xffffffffu, p_lo, 1);
        p_lo += __shfl_xor_sync(0xffffffffu, p_lo, 2);
        p_hi += __shfl_xor_sync(0xffffffffu, p_hi, 1);
        p_hi += __shfl_xor_sync(0xffffffffu, p_hi, 2);
        if (tg == 0) {
            sPart[warp_n * 128 + rl_lo] = p_lo;
            sPart[warp_n * 128 + rl_hi] = p_hi;
        }
    }
    __syncthreads();
    if (tid < 128) {
        float v = sPart[tid] + sPart[128 + tid] + sPart[256 + tid] + sPart[384 + tid];
        g_attP[(size_t)blockIdx.y * ROWS_TOTAL + row0 + tid] = v;
    }
}

// ============================================================================
// Kernel 3: softmax over P + weighted sum of encoder features
//   grid (B, 2): each block does 1024 of 2048 enc dims, 256 threads x float4
// ============================================================================
__global__ void __launch_bounds__(256) softmax_wsum_kernel(
    const float* __restrict__ enc, float* __restrict__ out) {
    int b = blockIdx.x;
    int half = blockIdx.y;
    int tid = threadIdx.x;
    __shared__ float red[256];
    __shared__ float w[256];

    float v = -1e30f;
    if (tid < P_SZ) {
        size_t idx = (size_t)b * P_SZ + tid;
        v = g_attP[idx] + g_attP[ROWS_TOTAL + idx] +
            g_attP[2 * ROWS_TOTAL + idx] + g_attP[3 * ROWS_TOTAL + idx];
    }
    red[tid] = v;
    __syncthreads();
    for (int s = 128; s > 0; s >>= 1) {
        if (tid < s) red[tid] = fmaxf(red[tid], red[tid + s]);
        __syncthreads();
    }
    float m = red[0];
    __syncthreads();
    float e = (tid < P_SZ) ? expf(v - m) : 0.f;
    red[tid] = e;
    __syncthreads();
    for (int s = 128; s > 0; s >>= 1) {
        if (tid < s) red[tid] += red[tid + s];
        __syncthreads();
    }
    float inv = 1.f / red[0];
    w[tid] = e * inv;
    __syncthreads();

    const float* base = enc + (size_t)b * P_SZ * ENC_D + half * 1024 + tid * 4;
    float4 acc = make_float4(0.f, 0.f, 0.f, 0.f);
#pragma unroll 4
    for (int p = 0; p < P_SZ; p++) {
        float4 x = *(const float4*)(base + (size_t)p * ENC_D);
        float wp = w[p];
        acc.x = fmaf(x.x, wp, acc.x);
        acc.y = fmaf(x.y, wp, acc.y);
        acc.z = fmaf(x.z, wp, acc.z);
        acc.w = fmaf(x.w, wp, acc.w);
    }
    *(float4*)(out + (size_t)b * ENC_D + half * 1024 + tid * 4) = acc;
}

// ============================================================================
// Launch
// ============================================================================
extern "C" void kernel_launch(void* const* d_in, const int* in_sizes, int n_in,
                              void* d_out, int out_size) {
    const float* encoder_out = (const float*)d_in[0];
    const float* decoder_out = (const float*)d_in[1];
    const float* W_enc       = (const float*)d_in[2];
    const float* b_enc       = (const float*)d_in[3];
    const float* W_dec       = (const float*)d_in[4];
    const float* b_dec       = (const float*)d_in[5];
    const float* W_fin       = (const float*)d_in[6];
    // d_in[7] = b_fin : dropped (softmax shift-invariant)
    float* out = (float*)d_out;

    decproj_kernel<<<B_SZ / 4, 512>>>(decoder_out, W_dec, b_dec);

    static int smem_set = 0;
    if (!smem_set) {
        cudaFuncSetAttribute(gemm_att_kernel, cudaFuncAttributeMaxDynamicSharedMemorySize, SMEM_TOTAL);
        smem_set = 1;
    }
    gemm_att_kernel<<<dim3(M_CTAS, N_CTAS), 256, SMEM_TOTAL>>>(encoder_out, W_enc, b_enc, W_fin);

    softmax_wsum_kernel<<<dim3(B_SZ, 2), 256>>>(encoder_out, out);
}

// round 14
// speedup vs baseline: 1.0010x; 1.0003x over previous
#include <cuda_runtime.h>
#include <cuda_bf16.h>
#include <cstdint>

// ============================================================================
// Problem: B=256, P=196, ENC=2048, WORD=512, ATT=512
//   att_enc = enc @ W_enc + b_enc              [B,P,512]  (105 GFLOP, dominant)
//   att_dec = dec @ W_dec + b_dec              [B,512]
//   att     = relu(att_enc + att_dec) . W_fin  -> [B,P]   (b_fin dropped: softmax-invariant)
//   w       = softmax_P(att)
//   out     = sum_p enc[b,p,:] * w[b,p]        [B,2048]
//
// tcgen05 is NOT available (harness ptxas targets plain sm_103, no 'a' features).
// GEMM uses mma.sync.m16n8k8 tf32 (sm_80+ feature, accepted by sm_103).
// ============================================================================

#define B_SZ   256
#define P_SZ   196
#define ENC_D  2048
#define WORD_D 512
#define ATT_D  512
#define ROWS_TOTAL (B_SZ * P_SZ)        // 50176
#define M_TILE 128
#define N_TILE 128
#define K_TILE 32
#define N_KT   (ENC_D / K_TILE)         // 64
#define M_CTAS (ROWS_TOTAL / M_TILE)    // 392
#define N_CTAS (ATT_D / N_TILE)         // 4

// ---- device scratch (no runtime allocation allowed) ----
__device__ __align__(16) float g_attdec[B_SZ * ATT_D];        // [256,512]
__device__ __align__(16) float g_attP[N_CTAS * ROWS_TOTAL];   // per-N-slice logit partials

// ============================================================================
// PTX helpers
// ============================================================================
__device__ __forceinline__ uint32_t smem_u32(const void* p) {
    uint32_t a;
    asm("{ .reg .u64 t; cvta.to.shared.u64 t, %1; cvt.u32.u64 %0, t; }" : "=r"(a) : "l"(p));
    return a;
}
#define CP_ASYNC16(dst_u32, src_ptr) \
    asm volatile("cp.async.cg.shared.global [%0], [%1], 16;" :: "r"(dst_u32), "l"(src_ptr) : "memory")
#define CP_ASYNC_COMMIT()   asm volatile("cp.async.commit_group;" ::: "memory")
#define CP_ASYNC_WAIT_ALL() asm volatile("cp.async.wait_group 0;" ::: "memory")

__device__ __forceinline__ uint32_t f2tf32(float x) {
    uint32_t y;
    asm("cvt.rna.tf32.f32 %0, %1;" : "=r"(y) : "f"(x));
    return y;
}
__device__ __forceinline__ void mma_tf32(float* d, const uint32_t* a, const uint32_t* b) {
    asm volatile(
        "mma.sync.aligned.m16n8k8.row.col.f32.tf32.tf32.f32 "
        "{%0,%1,%2,%3}, {%4,%5,%6,%7}, {%8,%9}, {%0,%1,%2,%3};"
        : "+f"(d[0]), "+f"(d[1]), "+f"(d[2]), "+f"(d[3])
        : "r"(a[0]), "r"(a[1]), "r"(a[2]), "r"(a[3]), "r"(b[0]), "r"(b[1]));
}

// ============================================================================
// SMEM layout (dynamic, bytes). Padded strides for conflict-free frag loads.
//   A tile: 128 rows x 32 k, stride 36 floats (144 B)
//   B tile:  32 k   x 128 n, stride 136 floats (544 B)
// ============================================================================
#define A_STRIDE_F 36
#define B_STRIDE_F 136
#define A_TILE_B   (M_TILE * A_STRIDE_F * 4)   // 18432
#define B_TILE_B   (K_TILE * B_STRIDE_F * 4)   // 17408
#define OFF_A(s)   ((s) * A_TILE_B)
#define OFF_B(s)   (2 * A_TILE_B + (s) * B_TILE_B)
#define OFF_ADEC0  (2 * A_TILE_B + 2 * B_TILE_B)        // 71680
#define OFF_ADEC1  (OFF_ADEC0 + 512)
#define OFF_WFIN   (OFF_ADEC0 + 1024)
#define OFF_PART   (OFF_ADEC0 + 1536)                   // 4 x 128 floats
#define SMEM_TOTAL (OFF_PART + 2048)                    // 75264

// ============================================================================
// Kernel 1: att_dec = decoder_out @ W_dec + b_dec   (4 batches / block)
// ============================================================================
__global__ void __launch_bounds__(512) decproj_kernel(
    const float* __restrict__ dec, const float* __restrict__ Wd, const float* __restrict__ bd) {
    __shared__ float sdec[4][WORD_D];
    int tid = threadIdx.x;
    int b0 = blockIdx.x * 4;
#pragma unroll
    for (int i = 0; i < 4; i++)
        sdec[i][tid] = dec[(size_t)(b0 + i) * WORD_D + tid];
    __syncthreads();
    float a0 = 0.f, a1 = 0.f, a2 = 0.f, a3 = 0.f;
#pragma unroll 4
    for (int k = 0; k < WORD_D; k++) {
        float w = Wd[(size_t)k * ATT_D + tid];
        a0 = fmaf(sdec[0][k], w, a0);
        a1 = fmaf(sdec[1][k], w, a1);
        a2 = fmaf(sdec[2][k], w, a2);
        a3 = fmaf(sdec[3][k], w, a3);
    }
    float bb = bd[tid];
    g_attdec[(size_t)(b0 + 0) * ATT_D + tid] = a0 + bb;
    g_attdec[(size_t)(b0 + 1) * ATT_D + tid] = a1 + bb;
    g_attdec[(size_t)(b0 + 2) * ATT_D + tid] = a2 + bb;
    g_attdec[(size_t)(b0 + 3) * ATT_D + tid] = a3 + bb;
}

// ============================================================================
// Kernel 2: tf32 mma.sync GEMM + fused relu/dot epilogue -> g_attP partials
//   grid (392, 4): CTA tile M=128 x N=128, K=2048 (64 stages of 32)
//   8 warps: warp_m = wid>>2 (2), warp_n = wid&3 (4); warp tile 64 x 32
// ============================================================================
__global__ void __launch_bounds__(256, 1) gemm_att_kernel(
    const float* __restrict__ enc,
    const float* __restrict__ W_enc,
    const float* __restrict__ b_enc,
    const float* __restrict__ W_fin) {
    extern __shared__ char smem[];
    const uint32_t sb = smem_u32(smem);
    const int tid = threadIdx.x;
    const int wid = tid >> 5, lane = tid & 31;
    const int warp_m = wid >> 2, warp_n = wid & 3;
    const int g = lane >> 2, tg = lane & 3;

    const int row0 = blockIdx.x * M_TILE;
    const int n0   = blockIdx.y * N_TILE;
    const int b0   = row0 / P_SZ;
    const int b1   = (row0 + M_TILE - 1) / P_SZ;

    // bias slices: sAdec = b_enc + att_dec (per batch), sWfin
    float* sAdec0 = (float*)(smem + OFF_ADEC0);
    float* sAdec1 = (float*)(smem + OFF_ADEC1);
    float* sWfin  = (float*)(smem + OFF_WFIN);
    if (tid < 128) {
        float be = b_enc[n0 + tid];
        sAdec0[tid] = be + g_attdec[(size_t)b0 * ATT_D + n0 + tid];
        sAdec1[tid] = be + g_attdec[(size_t)b1 * ATT_D + n0 + tid];
        sWfin[tid]  = W_fin[n0 + tid];
    }

    // ---- cp.async staging addresses ----
    // A: thread covers 4 float4: row = i*32 + tid/8, c4 = tid%8
    const int a_r = tid >> 3, a_c = tid & 7;
    const float* a_src = enc + (size_t)(row0 + a_r) * ENC_D + a_c * 4;
    const uint32_t a_dst = a_r * (A_STRIDE_F * 4) + a_c * 16;
    // B: thread covers 4 float4: k = i*8 + tid/32, c4 = tid%32
    const int b_k = tid >> 5, b_c = tid & 31;
    const float* b_src = W_enc + (size_t)b_k * ATT_D + n0 + b_c * 4;
    const uint32_t b_dst = b_k * (B_STRIDE_F * 4) + b_c * 16;

    // prologue: stage 0 <- tile 0
    {
        uint32_t ab = sb + OFF_A(0), bb = sb + OFF_B(0);
#pragma unroll
        for (int i = 0; i < 4; i++)
            CP_ASYNC16(ab + a_dst + i * 32 * (A_STRIDE_F * 4), a_src + (size_t)i * 32 * ENC_D);
#pragma unroll
        for (int i = 0; i < 4; i++)
            CP_ASYNC16(bb + b_dst + i * 8 * (B_STRIDE_F * 4), b_src + (size_t)i * 8 * ATT_D);
        CP_ASYNC_COMMIT();
        CP_ASYNC_WAIT_ALL();
    }
    __syncthreads();

    float acc[4][4][4];
#pragma unroll
    for (int mi = 0; mi < 4; mi++)
#pragma unroll
        for (int ni = 0; ni < 4; ni++)
#pragma unroll
            for (int r = 0; r < 4; r++) acc[mi][ni][r] = 0.f;

    // fragment smem offsets (floats)
    const int a_frag_base = (warp_m * 64 + g) * A_STRIDE_F + tg;   // + mi*16*36, + k8*8
    const int b_frag_base = tg * B_STRIDE_F + warp_n * 32 + g;     // + k8*8*136, + ni*8

    for (int c = 0; c < N_KT; ++c) {
        const int s = c & 1;
        // prefetch next tile into the other stage
        if (c + 1 < N_KT) {
            const size_t k_off = (size_t)(c + 1) * K_TILE;
            uint32_t ab = sb + OFF_A(s ^ 1), bbs = sb + OFF_B(s ^ 1);
#pragma unroll
            for (int i = 0; i < 4; i++)
                CP_ASYNC16(ab + a_dst + i * 32 * (A_STRIDE_F * 4),
                           a_src + (size_t)i * 32 * ENC_D + k_off);
#pragma unroll
            for (int i = 0; i < 4; i++)
                CP_ASYNC16(bbs + b_dst + i * 8 * (B_STRIDE_F * 4),
                           b_src + (size_t)(i * 8 + k_off) * ATT_D);
            CP_ASYNC_COMMIT();
        }

        const float* As = (const float*)(smem + OFF_A(s));
        const float* Bs = (const float*)(smem + OFF_B(s));
#pragma unroll
        for (int k8 = 0; k8 < 4; k8++) {
            uint32_t af[4][4], bf[4][2];
#pragma unroll
            for (int mi = 0; mi < 4; mi++) {
                const float* p = As + a_frag_base + mi * 16 * A_STRIDE_F + k8 * 8;
                af[mi][0] = f2tf32(p[0]);
                af[mi][1] = f2tf32(p[8 * A_STRIDE_F]);
                af[mi][2] = f2tf32(p[4]);
                af[mi][3] = f2tf32(p[8 * A_STRIDE_F + 4]);
            }
#pragma unroll
            for (int ni = 0; ni < 4; ni++) {
                const float* p = Bs + b_frag_base + k8 * 8 * B_STRIDE_F + ni * 8;
                bf[ni][0] = f2tf32(p[0]);
                bf[ni][1] = f2tf32(p[4 * B_STRIDE_F]);
            }
#pragma unroll
            for (int mi = 0; mi < 4; mi++)
#pragma unroll
                for (int ni = 0; ni < 4; ni++)
                    mma_tf32(acc[mi][ni], af[mi], bf[ni]);
        }

        if (c + 1 < N_KT) CP_ASYNC_WAIT_ALL();
        __syncthreads();
    }

    // ---- fused epilogue: relu(acc + bias + att_dec) . W_fin over this 128-n slice
    float* sPart = (float*)(smem + OFF_PART);   // [4][128]
#pragma unroll
    for (int mi = 0; mi < 4; mi++) {
        const int rl_lo = warp_m * 64 + mi * 16 + g;
        const int rl_hi = rl_lo + 8;
        const float* ad_lo = ((row0 + rl_lo) / P_SZ == b0) ? sAdec0 : sAdec1;
        const float* ad_hi = ((row0 + rl_hi) / P_SZ == b0) ? sAdec0 : sAdec1;
        float p_lo = 0.f, p_hi = 0.f;
#pragma unroll
        for (int ni = 0; ni < 4; ni++) {
            const int n = warp_n * 32 + ni * 8 + 2 * tg;
            float x;
            x = acc[mi][ni][0] + ad_lo[n];     p_lo = fmaf(fmaxf(x, 0.f), sWfin[n],     p_lo);
            x = acc[mi][ni][1] + ad_lo[n + 1]; p_lo = fmaf(fmaxf(x, 0.f), sWfin[n + 1], p_lo);
            x = acc[mi][ni][2] + ad_hi[n];     p_hi = fmaf(fmaxf(x, 0.f), sWfin[n],     p_hi);
            x = acc[mi][ni][3] + ad_hi[n + 1]; p_hi = fmaf(fmaxf(x, 0.f), sWfin[n + 1], p_hi);
        }
        // reduce over the 4 lanes of the quad
        p_lo += __shfl_xor_sync(0xffffffffu, p_lo, 1);
        p_lo += __shfl_xor_sync(0xffffffffu, p_lo, 2);
        p_hi += __shfl_xor_sync(0xffffffffu, p_hi, 1);
        p_hi += __shfl_xor_sync(0xffffffffu, p_hi, 2);
        if (tg == 0) {
            sPart[warp_n * 128 + rl_lo] = p_lo;
            sPart[warp_n * 128 + rl_hi] = p_hi;
        }
    }
    __syncthreads();
    if (tid < 128) {
        float v = sPart[tid] + sPart[128 + tid] + sPart[256 + tid] + sPart[384 + tid];
        g_attP[(size_t)blockIdx.y * ROWS_TOTAL + row0 + tid] = v;
    }
}

// ============================================================================
// Kernel 3: softmax over P + weighted sum of encoder features
//   grid (B, 2): each block does 1024 of 2048 enc dims, 256 threads x float4
// ============================================================================
__global__ void __launch_bounds__(256) softmax_wsum_kernel(
    const float* __restrict__ enc, float* __restrict__ out) {
    int b = blockIdx.x;
    int half = blockIdx.y;
    int tid = threadIdx.x;
    __shared__ float red[256];
    __shared__ float w[256];

    float v = -1e30f;
    if (tid < P_SZ) {
        size_t idx = (size_t)b * P_SZ + tid;
        v = g_attP[idx] + g_attP[ROWS_TOTAL + idx] +
            g_attP[2 * ROWS_TOTAL + idx] + g_attP[3 * ROWS_TOTAL + idx];
    }
    red[tid] = v;
    __syncthreads();
    for (int s = 128; s > 0; s >>= 1) {
        if (tid < s) red[tid] = fmaxf(red[tid], red[tid + s]);
        __syncthreads();
    }
    float m = red[0];
    __syncthreads();
    float e = (tid < P_SZ) ? expf(v - m) : 0.f;
    red[tid] = e;
    __syncthreads();
    for (int s = 128; s > 0; s >>= 1) {
        if (tid < s) red[tid] += red[tid + s];
        __syncthreads();
    }
    float inv = 1.f / red[0];
    w[tid] = e * inv;
    __syncthreads();

    const float* base = enc + (size_t)b * P_SZ * ENC_D + half * 1024 + tid * 4;
    float4 acc = make_float4(0.f, 0.f, 0.f, 0.f);
#pragma unroll 4
    for (int p = 0; p < P_SZ; p++) {
        float4 x = *(const float4*)(base + (size_t)p * ENC_D);
        float wp = w[p];
        acc.x = fmaf(x.x, wp, acc.x);
        acc.y = fmaf(x.y, wp, acc.y);
        acc.z = fmaf(x.z, wp, acc.z);
        acc.w = fmaf(x.w, wp, acc.w);
    }
    *(float4*)(out + (size_t)b * ENC_D + half * 1024 + tid * 4) = acc;
}

// ============================================================================
// Launch
// ============================================================================
extern "C" void kernel_launch(void* const* d_in, const int* in_sizes, int n_in,
                              void* d_out, int out_size) {
    const float* encoder_out = (const float*)d_in[0];
    const float* decoder_out = (const float*)d_in[1];
    const float* W_enc       = (const float*)d_in[2];
    const float* b_enc       = (const float*)d_in[3];
    const float* W_dec       = (const float*)d_in[4];
    const float* b_dec       = (const float*)d_in[5];
    const float* W_fin       = (const float*)d_in[6];
    // d_in[7] = b_fin : dropped (softmax shift-invariant)
    float* out = (float*)d_out;

    decproj_kernel<<<B_SZ / 4, 512>>>(decoder_out, W_dec, b_dec);

    static int smem_set = 0;
    if (!smem_set) {
        cudaFuncSetAttribute(gemm_att_kernel, cudaFuncAttributeMaxDynamicSharedMemorySize, SMEM_TOTAL);
        smem_set = 1;
    }
    gemm_att_kernel<<<dim3(M_CTAS, N_CTAS), 256, SMEM_TOTAL>>>(encoder_out, W_enc, b_enc, W_fin);

    softmax_wsum_kernel<<<dim3(B_SZ, 2), 256>>>(encoder_out, out);
}

// round 15
// speedup vs baseline: 1.0020x; 1.0010x over previous
#include <cuda_runtime.h>
#include <cuda_bf16.h>
#include <cstdint>

// ============================================================================
// Problem: B=256, P=196, ENC=2048, WORD=512, ATT=512
//   att_enc = enc @ W_enc + b_enc              [B,P,512]  (105 GFLOP, dominant)
//   att_dec = dec @ W_dec + b_dec              [B,512]
//   att     = relu(att_enc + att_dec) . W_fin  -> [B,P]   (b_fin dropped: softmax-invariant)
//   w       = softmax_P(att)
//   out     = sum_p enc[b,p,:] * w[b,p]        [B,2048]
//
// tcgen05 unavailable (harness ptxas targets plain sm_103). GEMM uses
// mma.sync.m16n8k8 tf32. Grid ordered N-fastest so the 4 N-slices of one
// M-tile run in the same wave -> A tile DRAM-fetched once, L2-hit 3x.
// ============================================================================

#define B_SZ   256
#define P_SZ   196
#define ENC_D  2048
#define WORD_D 512
#define ATT_D  512
#define ROWS_TOTAL (B_SZ * P_SZ)        // 50176
#define M_TILE 128
#define N_TILE 128
#define K_TILE 32
#define N_KT   (ENC_D / K_TILE)         // 64
#define M_CTAS (ROWS_TOTAL / M_TILE)    // 392
#define N_CTAS (ATT_D / N_TILE)         // 4

// ---- device scratch (no runtime allocation allowed) ----
__device__ __align__(16) float g_attdec[B_SZ * ATT_D];        // [256,512]
__device__ __align__(16) float g_attP[N_CTAS * ROWS_TOTAL];   // per-N-slice logit partials

// ============================================================================
// PTX helpers
// ============================================================================
__device__ __forceinline__ uint32_t smem_u32(const void* p) {
    uint32_t a;
    asm("{ .reg .u64 t; cvta.to.shared.u64 t, %1; cvt.u32.u64 %0, t; }" : "=r"(a) : "l"(p));
    return a;
}
#define CP_ASYNC16(dst_u32, src_ptr) \
    asm volatile("cp.async.cg.shared.global [%0], [%1], 16;" :: "r"(dst_u32), "l"(src_ptr) : "memory")
#define CP_ASYNC_COMMIT()    asm volatile("cp.async.commit_group;" ::: "memory")
#define CP_ASYNC_WAIT(n)     asm volatile("cp.async.wait_group %0;" :: "n"(n) : "memory")

__device__ __forceinline__ uint32_t f2tf32(float x) {
    uint32_t y;
    asm("cvt.rna.tf32.f32 %0, %1;" : "=r"(y) : "f"(x));
    return y;
}
__device__ __forceinline__ void mma_tf32(float* d, const uint32_t* a, const uint32_t* b) {
    asm volatile(
        "mma.sync.aligned.m16n8k8.row.col.f32.tf32.tf32.f32 "
        "{%0,%1,%2,%3}, {%4,%5,%6,%7}, {%8,%9}, {%0,%1,%2,%3};"
        : "+f"(d[0]), "+f"(d[1]), "+f"(d[2]), "+f"(d[3])
        : "r"(a[0]), "r"(a[1]), "r"(a[2]), "r"(a[3]), "r"(b[0]), "r"(b[1]));
}

// ============================================================================
// SMEM layout (dynamic, bytes). 3 pipeline stages.
//   A tile: 128 rows x 32 k, stride 36 floats (144 B)
//   B tile:  32 k   x 128 n, stride 136 floats (544 B)
// ============================================================================
#define A_STRIDE_F 36
#define B_STRIDE_F 136
#define A_TILE_B   (M_TILE * A_STRIDE_F * 4)   // 18432
#define B_TILE_B   (K_TILE * B_STRIDE_F * 4)   // 17408
#define N_STAGE    3
#define OFF_A(s)   ((s) * A_TILE_B)
#define OFF_B(s)   (N_STAGE * A_TILE_B + (s) * B_TILE_B)
#define OFF_ADEC0  (N_STAGE * A_TILE_B + N_STAGE * B_TILE_B)   // 107520
#define OFF_ADEC1  (OFF_ADEC0 + 512)
#define OFF_WFIN   (OFF_ADEC0 + 1024)
#define OFF_PART   (OFF_ADEC0 + 1536)                          // 4 x 128 floats
#define SMEM_TOTAL (OFF_PART + 2048)                           // 111104

// ============================================================================
// Kernel 1: att_dec = decoder_out @ W_dec + b_dec
//   grid 128 blocks x 128 threads; block = 2 batches, thread = 4 n (float4)
// ============================================================================
__global__ void __launch_bounds__(128) decproj_kernel(
    const float* __restrict__ dec, const float* __restrict__ Wd, const float* __restrict__ bd) {
    __shared__ float sdec[2][WORD_D];
    const int tid = threadIdx.x;
    const int b0 = blockIdx.x * 2;
    // load 2 decoder rows (1024 floats) via float4
    const float4* dsrc = (const float4*)(dec + (size_t)b0 * WORD_D);
#pragma unroll
    for (int i = 0; i < 2; i++)
        ((float4*)sdec)[tid + i * 128] = dsrc[tid + i * 128];
    __syncthreads();

    const int n4 = tid * 4;
    float4 a0 = make_float4(0.f, 0.f, 0.f, 0.f);
    float4 a1 = make_float4(0.f, 0.f, 0.f, 0.f);
#pragma unroll 8
    for (int k = 0; k < WORD_D; k++) {
        float4 w = *(const float4*)(Wd + (size_t)k * ATT_D + n4);
        float s0 = sdec[0][k], s1 = sdec[1][k];
        a0.x = fmaf(w.x, s0, a0.x); a0.y = fmaf(w.y, s0, a0.y);
        a0.z = fmaf(w.z, s0, a0.z); a0.w = fmaf(w.w, s0, a0.w);
        a1.x = fmaf(w.x, s1, a1.x); a1.y = fmaf(w.y, s1, a1.y);
        a1.z = fmaf(w.z, s1, a1.z); a1.w = fmaf(w.w, s1, a1.w);
    }
    float4 bb = *(const float4*)(bd + n4);
    a0.x += bb.x; a0.y += bb.y; a0.z += bb.z; a0.w += bb.w;
    a1.x += bb.x; a1.y += bb.y; a1.z += bb.z; a1.w += bb.w;
    *(float4*)(g_attdec + (size_t)(b0 + 0) * ATT_D + n4) = a0;
    *(float4*)(g_attdec + (size_t)(b0 + 1) * ATT_D + n4) = a1;
}

// ============================================================================
// Kernel 2: tf32 mma.sync GEMM + fused relu/dot epilogue -> g_attP partials
//   grid (4 n, 392 m): N fastest => 4 N-slices of an M-tile share its A tile
//   in L2 within a wave. CTA tile 128x128, K = 64 stages of 32.
//   8 warps: warp_m = wid>>2 (2), warp_n = wid&3 (4); warp tile 64 x 32.
//   3-stage cp.async pipeline, prefetch depth 2.
// ============================================================================
__global__ void __launch_bounds__(256, 1) gemm_att_kernel(
    const float* __restrict__ enc,
    const float* __restrict__ W_enc,
    const float* __restrict__ b_enc,
    const float* __restrict__ W_fin) {
    extern __shared__ char smem[];
    const uint32_t sb = smem_u32(smem);
    const int tid = threadIdx.x;
    const int wid = tid >> 5, lane = tid & 31;
    const int warp_m = wid >> 2, warp_n = wid & 3;
    const int g = lane >> 2, tg = lane & 3;

    const int n0   = blockIdx.x * N_TILE;
    const int row0 = blockIdx.y * M_TILE;
    const int b0   = row0 / P_SZ;
    const int b1   = (row0 + M_TILE - 1) / P_SZ;

    // bias slices: sAdec = b_enc + att_dec (per batch), sWfin
    float* sAdec0 = (float*)(smem + OFF_ADEC0);
    float* sAdec1 = (float*)(smem + OFF_ADEC1);
    float* sWfin  = (float*)(smem + OFF_WFIN);
    if (tid < 128) {
        float be = b_enc[n0 + tid];
        sAdec0[tid] = be + g_attdec[(size_t)b0 * ATT_D + n0 + tid];
        sAdec1[tid] = be + g_attdec[(size_t)b1 * ATT_D + n0 + tid];
        sWfin[tid]  = W_fin[n0 + tid];
    }

    // ---- cp.async staging addresses ----
    // A: thread covers 4 float4: row = i*32 + tid/8, c4 = tid%8
    const int a_r = tid >> 3, a_c = tid & 7;
    const float* a_src = enc + (size_t)(row0 + a_r) * ENC_D + a_c * 4;
    const uint32_t a_dst = a_r * (A_STRIDE_F * 4) + a_c * 16;
    // B: thread covers 4 float4: k = i*8 + tid/32, c4 = tid%32
    const int b_k = tid >> 5, b_c = tid & 31;
    const float* b_src = W_enc + (size_t)b_k * ATT_D + n0 + b_c * 4;
    const uint32_t b_dst = b_k * (B_STRIDE_F * 4) + b_c * 16;

    const uint32_t abuf[3] = {sb + OFF_A(0), sb + OFF_A(1), sb + OFF_A(2)};
    const uint32_t bbuf[3] = {sb + OFF_B(0), sb + OFF_B(1), sb + OFF_B(2)};

#define STAGE_LOAD(st, tile_idx) do {                                          \
        const size_t _ko = (size_t)(tile_idx) * K_TILE;                        \
        _Pragma("unroll")                                                      \
        for (int _i = 0; _i < 4; _i++)                                         \
            CP_ASYNC16(abuf[st] + a_dst + _i * 32 * (A_STRIDE_F * 4),          \
                       a_src + (size_t)_i * 32 * ENC_D + _ko);                 \
        _Pragma("unroll")                                                      \
        for (int _i = 0; _i < 4; _i++)                                         \
            CP_ASYNC16(bbuf[st] + b_dst + _i * 8 * (B_STRIDE_F * 4),           \
                       b_src + (size_t)(_i * 8 + _ko) * ATT_D);                \
        CP_ASYNC_COMMIT();                                                     \
    } while (0)

    // prologue: prefetch tiles 0 and 1
    STAGE_LOAD(0, 0);
    STAGE_LOAD(1, 1);

    float acc[4][4][4];
#pragma unroll
    for (int mi = 0; mi < 4; mi++)
#pragma unroll
        for (int ni = 0; ni < 4; ni++)
#pragma unroll
            for (int r = 0; r < 4; r++) acc[mi][ni][r] = 0.f;

    // fragment smem offsets (floats)
    const int a_frag_base = (warp_m * 64 + g) * A_STRIDE_F + tg;   // + mi*16*36, + k8*8
    const int b_frag_base = tg * B_STRIDE_F + warp_n * 32 + g;     // + k8*8*136, + ni*8

    int s = 0;
#pragma unroll 1
    for (int c = 0; c < N_KT; ++c) {
        if (c == N_KT - 1) { CP_ASYNC_WAIT(0); } else { CP_ASYNC_WAIT(1); }
        __syncthreads();

        // prefetch tile c+2 into the stage being retired after this compute
        if (c + 2 < N_KT) {
            int sn = s + 2; if (sn >= 3) sn -= 3;
            STAGE_LOAD(sn, c + 2);
        }

        const float* As = (const float*)(smem + OFF_A(0)) + (size_t)s * (A_TILE_B / 4);
        const float* Bs = (const float*)(smem + OFF_B(0)) + (size_t)s * (B_TILE_B / 4);
#pragma unroll
        for (int k8 = 0; k8 < 4; k8++) {
            uint32_t af[4][4], bf[4][2];
#pragma unroll
            for (int mi = 0; mi < 4; mi++) {
                const float* p = As + a_frag_base + mi * 16 * A_STRIDE_F + k8 * 8;
                af[mi][0] = f2tf32(p[0]);
                af[mi][1] = f2tf32(p[8 * A_STRIDE_F]);
                af[mi][2] = f2tf32(p[4]);
                af[mi][3] = f2tf32(p[8 * A_STRIDE_F + 4]);
            }
#pragma unroll
            for (int ni = 0; ni < 4; ni++) {
                const float* p = Bs + b_frag_base + k8 * 8 * B_STRIDE_F + ni * 8;
                bf[ni][0] = f2tf32(p[0]);
                bf[ni][1] = f2tf32(p[4 * B_STRIDE_F]);
            }
#pragma unroll
            for (int mi = 0; mi < 4; mi++)
#pragma unroll
                for (int ni = 0; ni < 4; ni++)
                    mma_tf32(acc[mi][ni], af[mi], bf[ni]);
        }

        s = (s == 2) ? 0 : s + 1;
    }
    __syncthreads();

    // ---- fused epilogue: relu(acc + bias + att_dec) . W_fin over this 128-n slice
    float* sPart = (float*)(smem + OFF_PART);   // [4][128]
#pragma unroll
    for (int mi = 0; mi < 4; mi++) {
        const int rl_lo = warp_m * 64 + mi * 16 + g;
        const int rl_hi = rl_lo + 8;
        const float* ad_lo = ((row0 + rl_lo) / P_SZ == b0) ? sAdec0 : sAdec1;
        const float* ad_hi = ((row0 + rl_hi) / P_SZ == b0) ? sAdec0 : sAdec1;
        float p_lo = 0.f, p_hi = 0.f;
#pragma unroll
        for (int ni = 0; ni < 4; ni++) {
            const int n = warp_n * 32 + ni * 8 + 2 * tg;
            float x;
            x = acc[mi][ni][0] + ad_lo[n];     p_lo = fmaf(fmaxf(x, 0.f), sWfin[n],     p_lo);
            x = acc[mi][ni][1] + ad_lo[n + 1]; p_lo = fmaf(fmaxf(x, 0.f), sWfin[n + 1], p_lo);
            x = acc[mi][ni][2] + ad_hi[n];     p_hi = fmaf(fmaxf(x, 0.f), sWfin[n],     p_hi);
            x = acc[mi][ni][3] + ad_hi[n + 1]; p_hi = fmaf(fmaxf(x, 0.f), sWfin[n + 1], p_hi);
        }
        p_lo += __shfl_xor_sync(0xffffffffu, p_lo, 1);
        p_lo += __shfl_xor_sync(0xffffffffu, p_lo, 2);
        p_hi += __shfl_xor_sync(0xffffffffu, p_hi, 1);
        p_hi += __shfl_xor_sync(0xffffffffu, p_hi, 2);
        if (tg == 0) {
            sPart[warp_n * 128 + rl_lo] = p_lo;
            sPart[warp_n * 128 + rl_hi] = p_hi;
        }
    }
    __syncthreads();
    if (tid < 128) {
        float v = sPart[tid] + sPart[128 + tid] + sPart[256 + tid] + sPart[384 + tid];
        g_attP[(size_t)blockIdx.x * ROWS_TOTAL + row0 + tid] = v;
    }
}

// ============================================================================
// Kernel 3: softmax over P + weighted sum of encoder features
//   grid (B, 2): each block does 1024 of 2048 enc dims, 256 threads x float4
// ============================================================================
__global__ void __launch_bounds__(256) softmax_wsum_kernel(
    const float* __restrict__ enc, float* __restrict__ out) {
    int b = blockIdx.x;
    int half = blockIdx.y;
    int tid = threadIdx.x;
    __shared__ float red[256];
    __shared__ float w[256];

    float v = -1e30f;
    if (tid < P_SZ) {
        size_t idx = (size_t)b * P_SZ + tid;
        v = g_attP[idx] + g_attP[ROWS_TOTAL + idx] +
            g_attP[2 * ROWS_TOTAL + idx] + g_attP[3 * ROWS_TOTAL + idx];
    }
    red[tid] = v;
    __syncthreads();
    for (int s = 128; s > 0; s >>= 1) {
        if (tid < s) red[tid] = fmaxf(red[tid], red[tid + s]);
        __syncthreads();
    }
    float m = red[0];
    __syncthreads();
    float e = (tid < P_SZ) ? expf(v - m) : 0.f;
    red[tid] = e;
    __syncthreads();
    for (int s = 128; s > 0; s >>= 1) {
        if (tid < s) red[tid] += red[tid + s];
        __syncthreads();
    }
    float inv = 1.f / red[0];
    w[tid] = e * inv;
    __syncthreads();

    const float* base = enc + (size_t)b * P_SZ * ENC_D + half * 1024 + tid * 4;
    float4 acc = make_float4(0.f, 0.f, 0.f, 0.f);
#pragma unroll 4
    for (int p = 0; p < P_SZ; p++) {
        float4 x = *(const float4*)(base + (size_t)p * ENC_D);
        float wp = w[p];
        acc.x = fmaf(x.x, wp, acc.x);
        acc.y = fmaf(x.y, wp, acc.y);
        acc.z = fmaf(x.z, wp, acc.z);
        acc.w = fmaf(x.w, wp, acc.w);
    }
    *(float4*)(out + (size_t)b * ENC_D + half * 1024 + tid * 4) = acc;
}

// ============================================================================
// Launch
// ============================================================================
extern "C" void kernel_launch(void* const* d_in, const int* in_sizes, int n_in,
                              void* d_out, int out_size) {
    const float* encoder_out = (const float*)d_in[0];
    const float* decoder_out = (const float*)d_in[1];
    const float* W_enc       = (const float*)d_in[2];
    const float* b_enc       = (const float*)d_in[3];
    const float* W_dec       = (const float*)d_in[4];
    const float* b_dec       = (const float*)d_in[5];
    const float* W_fin       = (const float*)d_in[6];
    // d_in[7] = b_fin : dropped (softmax shift-invariant)
    float* out = (float*)d_out;

    decproj_kernel<<<B_SZ / 2, 128>>>(decoder_out, W_dec, b_dec);

    cudaFuncSetAttribute(gemm_att_kernel, cudaFuncAttributeMaxDynamicSharedMemorySize, SMEM_TOTAL);
    // N fastest in grid.x so the 4 N-slices of one M-tile co-schedule (A L2 reuse)
    gemm_att_kernel<<<dim3(N_CTAS, M_CTAS), 256, SMEM_TOTAL>>>(encoder_out, W_enc, b_enc, W_fin);

    softmax_wsum_kernel<<<dim3(B_SZ, 2), 256>>>(encoder_out, out);
}